// round 12
// baseline (speedup 1.0000x reference)
#include <cuda_runtime.h>

// RSA_layer: output = c[-1] only  =>  softmax needed only for row i=1023.
//   s[j,u] = (fs @ w_hi)[j,u] + q[j]*w_dot[u],   q[j] = x . fs[j]
//   out[u] = sum_j fs[j,u]*exp(s[j,u]) / sum_j exp(s[j,u])
// Logits O(1) => exp without max-subtraction (validated rel_err ~3e-7).
// fs[j,v] = state[v*1024 + j + 1] for j < 1023;  fs[1023,v] = x[v]
//
// R12: R11 + serial-path cycle cuts (kernel runs at idle DVFS clocks, so
// critical-chain cycles convert ~1:1 to bench time):
//  - symmetric exchange epilogue: both halves publish partials, both compute
//    exp; half-0 REDGs z, half-1 REDGs c (balanced, 1 REDG per thread)
//  - poller: ALL threads acquire-spin on the counter (4 warps = staggered
//    polls), each thread then loads its own g_acc -> no s_ready/bar handoff.

#define UNITS 128
#define WIN   1024
#define NBLK  128         // worker blocks; block NBLK is the poller
#define TPB   256
#define JB    8           // j-rows per worker block
#define VH    64          // v-range per half

typedef unsigned long long u64;

__device__ float2 g_acc[UNITS];        // zeroed at load; reset each replay by poller
__device__ unsigned int g_cnt = 0;

__device__ __forceinline__ u64 pack2(float lo, float hi) {
    u64 r;
    asm("mov.b64 %0, {%1, %2};" : "=l"(r) : "f"(lo), "f"(hi));
    return r;
}
__device__ __forceinline__ void unpack2(u64 p, float& lo, float& hi) {
    asm("mov.b64 {%0, %1}, %2;" : "=f"(lo), "=f"(hi) : "l"(p));
}
__device__ __forceinline__ u64 ffma2(u64 a, u64 b, u64 c) {
    u64 d;
    asm("fma.rn.f32x2 %0, %1, %2, %3;" : "=l"(d) : "l"(a), "l"(b), "l"(c));
    return d;
}

__global__ void __launch_bounds__(TPB)
rsa_fused(const float* __restrict__ x,
          const float* __restrict__ state,
          const float* __restrict__ w,
          float* __restrict__ out)
{
    __shared__ __align__(16) float fs_sh[UNITS][JB];   // [v][j] (4KB)
    __shared__ float x_sh[UNITS];
    __shared__ float q_sh[JB];
    __shared__ __align__(16) float comb0[UNITS][JB];   // half-0 partials (4KB)
    __shared__ __align__(16) float comb1[UNITS][JB];   // half-1 partials (4KB)

    const int t = threadIdx.x;

    // ---------------- Poller block -------------------------------------------
    if (blockIdx.x == NBLK) {
        unsigned int v;
        do {   // every thread spins: 4 warps act as staggered polls of one line
            asm volatile("ld.acquire.gpu.global.u32 %0, [%1];"
                         : "=r"(v) : "l"(&g_cnt) : "memory");
        } while (v != NBLK);
        if (t < UNITS) {
            float2 p = g_acc[t];                      // ordered by own acquire
            out[t] = p.y / p.x;
            g_acc[t] = make_float2(0.0f, 0.0f);       // reset for next replay
        }
        if (t == 0) g_cnt = 0;
        return;
    }

    // ---------------- Worker blocks -----------------------------------------
    const int u  = t & (UNITS - 1);       // output column
    const int h  = t >> 7;                // v-half: 0 -> v[0,64), 1 -> v[64,128)
    const int j0 = blockIdx.x * JB;

    if (t < UNITS) x_sh[t] = x[t];

    // fs tile: 128v x 8j = 1024 floats, 4 per thread.
    #pragma unroll
    for (int k = 0; k < 4; k++) {
        int i = t + k * TPB;
        int v = i >> 3, j = i & (JB - 1);
        int jj = j0 + j;
        fs_sh[v][j] = (jj < WIN - 1) ? state[v * WIN + jj + 1] : x[v];
    }

    // This thread's 64-v slice of w_hi column u: 64 independent LDGs.
    const float* __restrict__ wu = w + h * VH * UNITS + u;  // w_hi[h*64+i][u]
    const float wd = w[2 * UNITS * UNITS + u];              // w_dot[u]
    float wr[VH];
    #pragma unroll
    for (int i = 0; i < VH; i++) wr[i] = wu[i * UNITS];

    __syncthreads();   // fs_sh / x_sh ready

    // q[j] = fs[j].x : 8 warps, warp jw owns one j (latency hidden by co-warp).
    {
        const int warp = t >> 5, lane = t & 31;
        float p = fs_sh[lane][warp]      * x_sh[lane]
                + fs_sh[lane + 32][warp] * x_sh[lane + 32]
                + fs_sh[lane + 64][warp] * x_sh[lane + 64]
                + fs_sh[lane + 96][warp] * x_sh[lane + 96];
        #pragma unroll
        for (int o = 16; o; o >>= 1) p += __shfl_xor_sync(0xffffffffu, p, o);
        if (lane == 0) q_sh[warp] = p;
    }

    // Partial GEMM over this half's v: {2x LDS.128 + 4x FFMA2} per v.
    u64 s01 = 0, s23 = 0, s45 = 0, s67 = 0;
    #pragma unroll
    for (int i = 0; i < VH; i++) {
        u64 w2 = pack2(wr[i], wr[i]);                 // alu-pipe
        const ulonglong2* fp = (const ulonglong2*)fs_sh[h * VH + i];
        ulonglong2 f = fp[0];                         // j0..3 broadcast
        s01 = ffma2(f.x, w2, s01);
        s23 = ffma2(f.y, w2, s23);
        ulonglong2 g = fp[1];                         // j4..7 broadcast
        s45 = ffma2(g.x, w2, s45);
        s67 = ffma2(g.y, w2, s67);
    }

    float sp[JB];
    unpack2(s01, sp[0], sp[1]);
    unpack2(s23, sp[2], sp[3]);
    unpack2(s45, sp[4], sp[5]);
    unpack2(s67, sp[6], sp[7]);

    // Symmetric exchange: BOTH halves publish (2x STS.128 each).
    {
        float (*mine)[JB] = (h == 0) ? comb0 : comb1;
        *(float4*)&mine[u][0] = make_float4(sp[0], sp[1], sp[2], sp[3]);
        *(float4*)&mine[u][4] = make_float4(sp[4], sp[5], sp[6], sp[7]);
    }
    __syncthreads();   // also publishes q_sh

    // Both halves compute full s and exp; half-0 reduces z, half-1 reduces c.
    {
        const float (*oth)[JB] = (h == 0) ? comb1 : comb0;
        float acc = 0.0f;
        #pragma unroll
        for (int j = 0; j < JB; j++) {
            float sj = sp[j] + oth[u][j];
            float e  = __expf(fmaf(q_sh[j], wd, sj));
            acc += (h == 0) ? e : e * fs_sh[u][j];    // z : c  (h warp-uniform)
        }
        float* dst = (h == 0) ? &g_acc[u].x : &g_acc[u].y;
        atomicAdd(dst, acc);                          // relaxed RED.ADD
    }

    // bar.sync + t0 release covers the whole block's REDGs (PTX model:
    // release composes through bar). No MEMBAR.
    __syncthreads();
    if (t == 0)
        asm volatile("red.add.release.gpu.global.u32 [%0], %1;"
                     :: "l"(&g_cnt), "r"(1u) : "memory");
}

extern "C" void kernel_launch(void* const* d_in, const int* in_sizes, int n_in,
                              void* d_out, int out_size)
{
    const float* x     = (const float*)d_in[0];   // input_tensor (1,128)
    const float* state = (const float*)d_in[1];   // state (128,1024)
    const float* w     = (const float*)d_in[2];   // w (257,128)
    // d_in[3] = b — cancels inside the softmax, unused.

    rsa_fused<<<NBLK + 1, TPB>>>(x, state, w, (float*)d_out);
}

// round 13
// speedup vs baseline: 1.1905x; 1.1905x over previous
#include <cuda_runtime.h>

// RSA_layer: output = c[-1] only  =>  softmax needed only for row i=1023.
//   s[j,u] = (fs @ w_hi)[j,u] + q[j]*w_dot[u],   q[j] = x . fs[j]
//   out[u] = sum_j fs[j,u]*exp(s[j,u]) / sum_j exp(s[j,u])
// Logits O(1) => exp without max-subtraction (validated rel_err ~3e-7).
// fs[j,v] = state[v*1024 + j + 1] for j < 1023;  fs[1023,v] = x[v]
//
// R13 = R11 worker body (measured best, 10.78us) + single-WARP poller:
// warp 0 of the poller block spins on g_cnt (32 lanes, one line -> one
// wavefront per poll, same LTS pressure as a 1-thread spin; R12 showed
// 8-warp polling contends with workers' releases and REGRESSES 2us), then
// each lane finalizes 4 u's with LDG.128/STG.128. No smem handoff, no bar.

#define UNITS 128
#define WIN   1024
#define NBLK  128         // worker blocks; block NBLK is the poller
#define TPB   256
#define JB    8           // j-rows per worker block
#define VH    64          // v-range per half

typedef unsigned long long u64;

__device__ float2 g_acc[UNITS];        // zeroed at load; reset each replay by poller
__device__ unsigned int g_cnt = 0;

__device__ __forceinline__ u64 pack2(float lo, float hi) {
    u64 r;
    asm("mov.b64 %0, {%1, %2};" : "=l"(r) : "f"(lo), "f"(hi));
    return r;
}
__device__ __forceinline__ void unpack2(u64 p, float& lo, float& hi) {
    asm("mov.b64 {%0, %1}, %2;" : "=f"(lo), "=f"(hi) : "l"(p));
}
__device__ __forceinline__ u64 ffma2(u64 a, u64 b, u64 c) {
    u64 d;
    asm("fma.rn.f32x2 %0, %1, %2, %3;" : "=l"(d) : "l"(a), "l"(b), "l"(c));
    return d;
}

__global__ void __launch_bounds__(TPB)
rsa_fused(const float* __restrict__ x,
          const float* __restrict__ state,
          const float* __restrict__ w,
          float* __restrict__ out)
{
    __shared__ __align__(16) float fs_sh[UNITS][JB];   // [v][j], j contiguous (4KB)
    __shared__ float x_sh[UNITS];
    __shared__ float q_sh[JB];
    __shared__ __align__(16) float comb[UNITS][JB];    // half-1 GEMM partials (4KB)

    const int t = threadIdx.x;

    // ---------------- Poller block: warp 0 only ------------------------------
    if (blockIdx.x == NBLK) {
        if (t < 32) {
            unsigned int v;
            do {   // 32 lanes, same address -> one wavefront per poll iter
                asm volatile("ld.acquire.gpu.global.u32 %0, [%1];"
                             : "=r"(v) : "l"(&g_cnt) : "memory");
            } while (v != NBLK);
            // Each lane finalizes u = 4t .. 4t+3 (own acquire orders these).
            float4 p0 = *(const float4*)&g_acc[4 * t];      // z0,c0,z1,c1
            float4 p1 = *(const float4*)&g_acc[4 * t + 2];  // z2,c2,z3,c3
            *(float4*)&out[4 * t] =
                make_float4(p0.y / p0.x, p0.w / p0.z, p1.y / p1.x, p1.w / p1.z);
            float4 zz = make_float4(0.f, 0.f, 0.f, 0.f);
            *(float4*)&g_acc[4 * t]     = zz;               // reset for replay
            *(float4*)&g_acc[4 * t + 2] = zz;
            if (t == 0) g_cnt = 0;
        }
        return;
    }

    // ---------------- Worker blocks -----------------------------------------
    const int u  = t & (UNITS - 1);       // output column
    const int h  = t >> 7;                // v-half: 0 -> v[0,64), 1 -> v[64,128)
    const int j0 = blockIdx.x * JB;

    if (t < UNITS) x_sh[t] = x[t];

    // fs tile: 128v x 8j = 1024 floats, 4 per thread.
    #pragma unroll
    for (int k = 0; k < 4; k++) {
        int i = t + k * TPB;
        int v = i >> 3, j = i & (JB - 1);
        int jj = j0 + j;
        fs_sh[v][j] = (jj < WIN - 1) ? state[v * WIN + jj + 1] : x[v];
    }

    // This thread's 64-v slice of w_hi column u: 64 independent LDGs.
    const float* __restrict__ wu = w + h * VH * UNITS + u;  // w_hi[h*64+i][u]
    const float wd = w[2 * UNITS * UNITS + u];              // w_dot[u]
    float wr[VH];
    #pragma unroll
    for (int i = 0; i < VH; i++) wr[i] = wu[i * UNITS];

    __syncthreads();   // fs_sh / x_sh ready

    // q[j] = fs[j].x : 8 warps, warp jw owns one j.
    {
        const int warp = t >> 5, lane = t & 31;
        float p = fs_sh[lane][warp]      * x_sh[lane]
                + fs_sh[lane + 32][warp] * x_sh[lane + 32]
                + fs_sh[lane + 64][warp] * x_sh[lane + 64]
                + fs_sh[lane + 96][warp] * x_sh[lane + 96];
        #pragma unroll
        for (int o = 16; o; o >>= 1) p += __shfl_xor_sync(0xffffffffu, p, o);
        if (lane == 0) q_sh[warp] = p;
    }

    // Partial GEMM over this half's v: {2x LDS.128 + 4x FFMA2} per v.
    u64 s01 = 0, s23 = 0, s45 = 0, s67 = 0;
    #pragma unroll
    for (int i = 0; i < VH; i++) {
        u64 w2 = pack2(wr[i], wr[i]);                 // alu-pipe
        const ulonglong2* fp = (const ulonglong2*)fs_sh[h * VH + i];
        ulonglong2 f = fp[0];                         // j0..3 broadcast
        s01 = ffma2(f.x, w2, s01);
        s23 = ffma2(f.y, w2, s23);
        ulonglong2 g = fp[1];                         // j4..7 broadcast
        s45 = ffma2(g.x, w2, s45);
        s67 = ffma2(g.y, w2, s67);
    }

    float sp[JB];
    unpack2(s01, sp[0], sp[1]);
    unpack2(s23, sp[2], sp[3]);
    unpack2(s45, sp[4], sp[5]);
    unpack2(s67, sp[6], sp[7]);

    // Half-1 publishes its partials (2x STS.128).
    if (h == 1) {
        *(float4*)&comb[u][0] = make_float4(sp[0], sp[1], sp[2], sp[3]);
        *(float4*)&comb[u][4] = make_float4(sp[4], sp[5], sp[6], sp[7]);
    }
    __syncthreads();   // also publishes q_sh

    // Half-0 combines, applies q*wd, REDG-accumulates (z,c) into g_acc.
    if (h == 0) {
        float z = 0.0f, c = 0.0f;
        #pragma unroll
        for (int j = 0; j < JB; j++) {
            float sj = sp[j] + comb[u][j];
            float e  = __expf(fmaf(q_sh[j], wd, sj));
            z += e;
            c = fmaf(e, fs_sh[u][j], c);              // fs[j][u]
        }
        atomicAdd(&g_acc[u].x, z);                    // relaxed RED.ADD
        atomicAdd(&g_acc[u].y, c);
    }

    // bar.sync + t0 release covers the block's REDGs (PTX model: release
    // composes through bar). No MEMBAR.
    __syncthreads();
    if (t == 0)
        asm volatile("red.add.release.gpu.global.u32 [%0], %1;"
                     :: "l"(&g_cnt), "r"(1u) : "memory");
}

extern "C" void kernel_launch(void* const* d_in, const int* in_sizes, int n_in,
                              void* d_out, int out_size)
{
    const float* x     = (const float*)d_in[0];   // input_tensor (1,128)
    const float* state = (const float*)d_in[1];   // state (128,1024)
    const float* w     = (const float*)d_in[2];   // w (257,128)
    // d_in[3] = b — cancels inside the softmax, unused.

    rsa_fused<<<NBLK + 1, TPB>>>(x, state, w, (float*)d_out);
}